// round 2
// baseline (speedup 1.0000x reference)
#include <cuda_runtime.h>
#include <cstdint>
#include <algorithm>

// Problem constants
#define HH   16
#define TPP  16
#define KKK  16
#define TTT  2048
#define NCOL 513                     // 2*H*K + 1
#define NWORK (1u << 23)             // H*T*K*TP = 16*2048*16*16 = 8388608
#define EMBN 1000000

struct PermParams {
    unsigned short posP[256];   // output column of +result[r]
    unsigned short posM[256];   // output column of -result[r]
    unsigned short posMid;      // output column of ori
    unsigned short pad;
};

// cfg bits: 1 = pos_idx is d_in[2] (inputs swapped vs assumed order)
//           2 = pos_idx stored as int32 (not int64)
//           4 = locations stored as int32 (not int64)
__device__ int g_cfg;

// ---------------------------------------------------------------------------
// Threefry-2x32, 20 rounds (JAX-compatible)
// ---------------------------------------------------------------------------
__host__ __device__ __forceinline__ uint32_t rotl32(uint32_t v, int r) {
#ifdef __CUDA_ARCH__
    return __funnelshift_l(v, v, r);
#else
    return (v << r) | (v >> (32 - r));
#endif
}

#define TF_R(x0, x1, R) { x0 += x1; x1 = rotl32(x1, R) ^ x0; }

__host__ __device__ __forceinline__ void tf2x32(uint32_t k0, uint32_t k1,
                                                uint32_t x0, uint32_t x1,
                                                uint32_t& o0, uint32_t& o1) {
    const uint32_t ks0 = k0, ks1 = k1, ks2 = k0 ^ k1 ^ 0x1BD11BDAu;
    x0 += ks0; x1 += ks1;
    TF_R(x0, x1, 13) TF_R(x0, x1, 15) TF_R(x0, x1, 26) TF_R(x0, x1, 6)
    x0 += ks1; x1 += ks2 + 1u;
    TF_R(x0, x1, 17) TF_R(x0, x1, 29) TF_R(x0, x1, 16) TF_R(x0, x1, 24)
    x0 += ks2; x1 += ks0 + 2u;
    TF_R(x0, x1, 13) TF_R(x0, x1, 15) TF_R(x0, x1, 26) TF_R(x0, x1, 6)
    x0 += ks0; x1 += ks1 + 3u;
    TF_R(x0, x1, 17) TF_R(x0, x1, 29) TF_R(x0, x1, 16) TF_R(x0, x1, 24)
    x0 += ks1; x1 += ks2 + 4u;
    TF_R(x0, x1, 13) TF_R(x0, x1, 15) TF_R(x0, x1, 26) TF_R(x0, x1, 6)
    x0 += ks2; x1 += ks0 + 5u;
    o0 = x0; o1 = x1;
}

// ---------------------------------------------------------------------------
// Probe kernel: resolve input order + integer widths from data patterns.
//  - pos_idx values are < 2^20; float bits of uniform(0,1) norm are >= 0x39000000
//  - int64 pos_idx: odd 32-bit words (high halves) are all zero
//  - int64 locations: odd words are 0 or 0xFFFFFFFF (sign extension of |v|<2^16)
// ---------------------------------------------------------------------------
__global__ void cfg_kernel(const uint32_t* __restrict__ a,   // d_in[1]
                           const uint32_t* __restrict__ b,   // d_in[2]
                           const uint32_t* __restrict__ loc) // d_in[0]
{
    int cfg = 0;
    const bool aPos = (a[0] < (1u << 20));
    const bool bPos = (b[0] < (1u << 20));
    const uint32_t* p = a;
    if (bPos && !aPos) { cfg |= 1; p = b; }
    // pos_idx width: int64 => high words all zero
    if ((p[1] | p[3] | p[5] | p[7]) != 0u) cfg |= 2;
    // locations width: int64 => odd words are sign extensions
    bool loc64 = true;
    #pragma unroll
    for (int w = 1; w < 16; w += 2) {
        uint32_t h = loc[w];
        if (h != 0u && h != 0xFFFFFFFFu) loc64 = false;
    }
    if (!loc64) cfg |= 4;
    g_cfg = cfg;
}

// ---------------------------------------------------------------------------
// Main kernel: one thread per (level i, row t, rep k, dim tp).
// Flattened index j == the JAX random_bits counter for that element.
// Each thread does ONE Threefry eval and writes the two output elements
// (+result and -result) that share it.
// ---------------------------------------------------------------------------
__global__ void __launch_bounds__(256)
crit_kernel(const void* __restrict__ locations,
            const void* __restrict__ in1,
            const void* __restrict__ in2,
            float* __restrict__ out,
            uint32_t k2a, uint32_t k2b,
            PermParams P) {
    const uint32_t j = blockIdx.x * blockDim.x + threadIdx.x;

    // j = ((i*T + t)*K + k)*TP + tp   (row-major over (H, T, K, TP))
    const uint32_t tp = j & 15u;
    const uint32_t k  = (j >> 4) & 15u;
    const uint32_t t  = (j >> 8) & 2047u;
    const uint32_t i  = j >> 19;

    const int cfg = g_cfg;
    const void*  posv = (cfg & 1) ? in2 : in1;
    const float* nrmp = (cfg & 1) ? (const float*)in1 : (const float*)in2;

    long long pidx = (cfg & 2) ? (long long)((const int*)posv)[t]
                               : ((const long long*)posv)[t];
    if (pidx < 0) pidx = 0;
    if (pidx >= EMBN) pidx = EMBN - 1;

    const int ori = (cfg & 4)
        ? ((const int*)locations)[pidx * TPP + tp]
        : (int)((const long long*)locations)[pidx * TPP + tp];
    const float nrm = nrmp[t];

    // Threefry: lower-bits word of randint; partitionable counters (0, j)
    uint32_t b1, b2;
    tf2x32(k2a, k2b, 0u, j, b1, b2);

    const uint32_t lvlmask = (1u << i) - 1u;
    const int cand = ori ^ (int)(1u << i) ^ (int)(b2 & lvlmask);

    // distance(cand, ori) and distance(-cand, ori)
    const uint32_t ax = (uint32_t)(abs(cand) ^ abs(ori));
    const int e = 32 - __clz(ax + 1u);               // bit length == frexp exponent
    const float base = (1.0f - (float)e * 0.0625f) * nrm;
    const bool oriNeg = (ori < 0);
    const float vp = ((cand < 0) == oriNeg) ? base : -base;  // sign(+cand)*sign(ori)
    const float vm = ((cand > 0) == oriNeg) ? base : -base;  // sign(-cand)*sign(ori)

    const int r = (int)(i * 16u + k);                // flattened (level, rep) index
    float* row = out + (size_t)t * (NCOL * TPP) + tp;
    row[(int)P.posP[r] * TPP] = vp;
    row[(int)P.posM[r] * TPP] = vm;

    if (r == 0) {                                    // middle column: distance(ori, ori)
        row[(int)P.posMid * TPP] = 0.9375f * nrm;    // (1 - 1/16) * norm
    }
}

// ---------------------------------------------------------------------------
// Host: derive all Threefry keys + the 513-column permutation (deterministic),
// pass the inverse permutation by value.
// ---------------------------------------------------------------------------
extern "C" void kernel_launch(void* const* d_in, const int* in_sizes, int n_in,
                              void* d_out, int out_size) {
    const void* loc = d_in[0];          // locations (EMB, 16) — largest input
    const void* in1 = d_in[1];
    const void* in2 = d_in[2];
    float* out = (float*)d_out;

    // key = jax.random.key(42) -> (0, 42)
    // partitionable split: split(key)[i] = TF(key, (0, i))
    uint32_t kmask0, kmask1, kperm0, kperm1;
    tf2x32(0u, 42u, 0u, 0u, kmask0, kmask1);   // kmask
    tf2x32(0u, 42u, 0u, 1u, kperm0, kperm1);   // kperm

    // randint(kmask,...): k1,k2 = split(kmask); lower_bits keyed by k2
    uint32_t k2a, k2b;
    tf2x32(kmask0, kmask1, 0u, 1u, k2a, k2b);

    // permutation(kperm, 513): one sort round; subkey = split(kperm)[1]
    uint32_t sk0, sk1;
    tf2x32(kperm0, kperm1, 0u, 1u, sk0, sk1);

    uint32_t skeys[NCOL];
    int idx[NCOL];
    for (int c = 0; c < NCOL; c++) {
        uint32_t b1, b2;
        tf2x32(sk0, sk1, 0u, (uint32_t)c, b1, b2);
        skeys[c] = b1 ^ b2;                    // 32-bit fold of the 64-bit draw
        idx[c] = c;
    }
    std::stable_sort(idx, idx + NCOL,
                     [&](int a, int b) { return skeys[a] < skeys[b]; });
    // idx[c] = perm[c]: output column c holds candidate perm[c]
    PermParams P;
    P.posMid = 0; P.pad = 0;
    for (int c = 0; c < NCOL; c++) {
        int p = idx[c];
        if (p < 256)        P.posP[p] = (unsigned short)c;
        else if (p == 256)  P.posMid  = (unsigned short)c;
        else                P.posM[p - 257] = (unsigned short)c;
    }

    cfg_kernel<<<1, 1>>>((const uint32_t*)in1, (const uint32_t*)in2,
                         (const uint32_t*)loc);

    const int threads = 256;
    const int blocks = (int)(NWORK / threads);   // 32768
    crit_kernel<<<blocks, threads>>>(loc, in1, in2, out, k2a, k2b, P);
}

// round 3
// speedup vs baseline: 1.2236x; 1.2236x over previous
#include <cuda_runtime.h>
#include <cstdint>
#include <algorithm>

// Problem constants
#define TPP  16
#define NCOL 513                      // 2*H*K + 1
#define EMBN 1000000
#define NTHREADS_TOTAL (1u << 22)     // NWORK/2: each thread handles 2 elements

struct PermParams {
    unsigned short posP[256];   // output column of +result[r]
    unsigned short posM[256];   // output column of -result[r]
    unsigned short posMid;      // output column of ori
    unsigned short pad;
};

// Rotation multipliers (1<<R) passed at runtime so ptxas emits IMAD.WIDE
// (fma pipe) instead of strength-reducing to SHF (alu pipe).
struct RotMuls { uint32_t m13, m15, m6, m17, m29, m24; };

// ---------------------------------------------------------------------------
// Threefry-2x32 (host side, for key/permutation derivation)
// ---------------------------------------------------------------------------
static inline uint32_t h_rotl32(uint32_t v, int r) {
    return (v << r) | (v >> (32 - r));
}
#define HTF_R(x0, x1, R) { x0 += x1; x1 = h_rotl32(x1, R) ^ x0; }
static void h_tf2x32(uint32_t k0, uint32_t k1, uint32_t x0, uint32_t x1,
                     uint32_t& o0, uint32_t& o1) {
    const uint32_t ks0 = k0, ks1 = k1, ks2 = k0 ^ k1 ^ 0x1BD11BDAu;
    x0 += ks0; x1 += ks1;
    HTF_R(x0, x1, 13) HTF_R(x0, x1, 15) HTF_R(x0, x1, 26) HTF_R(x0, x1, 6)
    x0 += ks1; x1 += ks2 + 1u;
    HTF_R(x0, x1, 17) HTF_R(x0, x1, 29) HTF_R(x0, x1, 16) HTF_R(x0, x1, 24)
    x0 += ks2; x1 += ks0 + 2u;
    HTF_R(x0, x1, 13) HTF_R(x0, x1, 15) HTF_R(x0, x1, 26) HTF_R(x0, x1, 6)
    x0 += ks0; x1 += ks1 + 3u;
    HTF_R(x0, x1, 17) HTF_R(x0, x1, 29) HTF_R(x0, x1, 16) HTF_R(x0, x1, 24)
    x0 += ks1; x1 += ks2 + 4u;
    HTF_R(x0, x1, 13) HTF_R(x0, x1, 15) HTF_R(x0, x1, 26) HTF_R(x0, x1, 6)
    x0 += ks2; x1 += ks0 + 5u;
    o0 = x0; o1 = x1;
}

// ---------------------------------------------------------------------------
// Main kernel: one thread per pair of adjacent elements (j0 = 2*tid, j1 = j0+1).
// j == JAX random_bits counter, row-major over (H=16, T=2048, K=16, TP=16).
// Two interleaved Threefry chains; pipe-balanced rounds:
//   - adds as IMAD via runtime `one` (fma pipe)
//   - 3 of 4 rotates per group via IMAD.WIDE + fused LOP3 (fma+alu)
//   - 1 of 4 rotates via SHF (alu)
// ---------------------------------------------------------------------------
__global__ void __launch_bounds__(256)
crit_kernel(const void* __restrict__ loc,
            const void* __restrict__ in1,
            const void* __restrict__ in2,
            float* __restrict__ out,
            uint32_t k2a, uint32_t k2b, uint32_t one,
            RotMuls RM, PermParams P) {
    const uint32_t tid = blockIdx.x * 256u + threadIdx.x;
    const uint32_t j0 = tid * 2u;
    const uint32_t j1 = j0 + 1u;

    const uint32_t tp0 = j0 & 15u;          // even
    const uint32_t k   = (j0 >> 4) & 15u;
    const uint32_t t   = (j0 >> 8) & 2047u;
    const uint32_t i   = j0 >> 19;

    // ---- input-layout probe (uniform broadcast loads, L1-hit after warmup) ----
    const uint4 A0 = ((const uint4*)in1)[0];
    const uint4 A1 = ((const uint4*)in1)[1];
    const uint4 B0 = ((const uint4*)in2)[0];
    const uint4 B1 = ((const uint4*)in2)[1];
    const uint4 L0 = ((const uint4*)loc)[0];
    const uint4 L1 = ((const uint4*)loc)[1];
    // pos_idx values < 2^20; uniform(0,1) float bits are >= ~0x39000000
    const bool aPos = (A0.x < (1u << 20));
    const void*  posv = aPos ? in1 : in2;
    const float* nrmp = aPos ? (const float*)in2 : (const float*)in1;
    const uint4 Pw0 = aPos ? A0 : B0;
    const uint4 Pw1 = aPos ? A1 : B1;
    const bool pos64 = ((Pw0.y | Pw0.w | Pw1.y | Pw1.w) == 0u);
    const bool loc64 = (L0.y == 0u || L0.y == 0xFFFFFFFFu) &&
                       (L0.w == 0u || L0.w == 0xFFFFFFFFu) &&
                       (L1.y == 0u || L1.y == 0xFFFFFFFFu) &&
                       (L1.w == 0u || L1.w == 0xFFFFFFFFu);

    long long pidx = pos64 ? ((const long long*)posv)[t]
                           : (long long)((const int*)posv)[t];
    if (pidx < 0) pidx = 0;
    if (pidx >= EMBN) pidx = EMBN - 1;

    int ori0, ori1;
    if (loc64) {
        const longlong2 L = ((const longlong2*)loc)[(pidx * TPP + tp0) >> 1];
        ori0 = (int)L.x; ori1 = (int)L.y;
    } else {
        const int2 L = ((const int2*)loc)[(pidx * TPP + tp0) >> 1];
        ori0 = L.x; ori1 = L.y;
    }
    const float nrm = nrmp[t];

    // ---- dual Threefry-2x32, 20 rounds ----
    const uint32_t ks0 = k2a, ks1 = k2b, ks2 = k2a ^ k2b ^ 0x1BD11BDAu;
    uint32_t xa0 = ks0, xa1 = j0 + ks1;
    uint32_t xb0 = ks0, xb1 = j1 + ks1;

#define QADD(a, b) ((a) * one + (b))                     /* IMAD, fma pipe */
#define RW(x0, x1, M) {                                                       \
    x0 = QADD(x0, x1);                                                        \
    uint64_t w_ = (uint64_t)(x1) * (uint64_t)(M);        /* IMAD.WIDE */      \
    (x1) = ((uint32_t)(w_ >> 32) | (uint32_t)w_) ^ (x0); /* fused LOP3 */     \
}
#define RS(x0, x1, R) {                                                       \
    x0 = QADD(x0, x1);                                                        \
    (x1) = __funnelshift_l((x1), (x1), (R)) ^ (x0);      /* SHF + LOP */      \
}
#define GRP_A                                                                 \
    RW(xa0, xa1, RM.m13) RW(xb0, xb1, RM.m13)                                 \
    RW(xa0, xa1, RM.m15) RW(xb0, xb1, RM.m15)                                 \
    RS(xa0, xa1, 26)     RS(xb0, xb1, 26)                                     \
    RW(xa0, xa1, RM.m6)  RW(xb0, xb1, RM.m6)
#define GRP_B                                                                 \
    RW(xa0, xa1, RM.m17) RW(xb0, xb1, RM.m17)                                 \
    RW(xa0, xa1, RM.m29) RW(xb0, xb1, RM.m29)                                 \
    RS(xa0, xa1, 16)     RS(xb0, xb1, 16)                                     \
    RW(xa0, xa1, RM.m24) RW(xb0, xb1, RM.m24)
#define INJ(cA, cB) { xa0 += (cA); xa1 += (cB); xb0 += (cA); xb1 += (cB); }

    GRP_A
    INJ(ks1, ks2 + 1u)
    GRP_B
    INJ(ks2, ks0 + 2u)
    GRP_A
    INJ(ks0, ks1 + 3u)
    GRP_B
    INJ(ks1, ks2 + 4u)
    GRP_A
    const uint32_t b2a = xa1 + ks0 + 5u;   // final o1 (o0 not needed)
    const uint32_t b2b = xb1 + ks0 + 5u;

    // ---- candidates + distance ----
    const uint32_t lvlmask = (1u << i) - 1u;
    const int flip = (int)(1u << i);
    const int cand0 = ori0 ^ flip ^ (int)(b2a & lvlmask);
    const int cand1 = ori1 ^ flip ^ (int)(b2b & lvlmask);

    const uint32_t ax0 = (uint32_t)(abs(cand0) ^ abs(ori0));
    const uint32_t ax1 = (uint32_t)(abs(cand1) ^ abs(ori1));
    const int e0 = 32 - __clz(ax0 + 1u);       // bit length == frexp exponent
    const int e1 = 32 - __clz(ax1 + 1u);
    const float base0 = (1.0f - (float)e0 * 0.0625f) * nrm;
    const float base1 = (1.0f - (float)e1 * 0.0625f) * nrm;
    const bool n0 = (ori0 < 0), n1 = (ori1 < 0);
    const float vp0 = (((cand0 < 0) == n0) ? base0 : -base0);
    const float vm0 = (((cand0 > 0) == n0) ? base0 : -base0);
    const float vp1 = (((cand1 < 0) == n1) ? base1 : -base1);
    const float vm1 = (((cand1 > 0) == n1) ? base1 : -base1);

    // ---- scatter via precomputed permutation ----
    const int r = (int)(i * 16u + k);
    float* row = out + (size_t)t * (NCOL * TPP) + tp0;
    const int cP = (int)P.posP[r];
    const int cM = (int)P.posM[r];
    *(float2*)(row + cP * TPP) = make_float2(vp0, vp1);
    *(float2*)(row + cM * TPP) = make_float2(vm0, vm1);
    if (r == 0) {
        const float mid = 0.9375f * nrm;       // (1 - 1/16) * norm
        *(float2*)(row + (int)P.posMid * TPP) = make_float2(mid, mid);
    }
}

// ---------------------------------------------------------------------------
// Host: derive Threefry keys + 513-column permutation (deterministic).
// ---------------------------------------------------------------------------
extern "C" void kernel_launch(void* const* d_in, const int* in_sizes, int n_in,
                              void* d_out, int out_size) {
    const void* loc = d_in[0];          // locations (EMB, 16)
    const void* in1 = d_in[1];
    const void* in2 = d_in[2];
    float* out = (float*)d_out;

    // key = jax.random.key(42) -> (0, 42); partitionable split(key)[i] = TF(key,(0,i))
    uint32_t kmask0, kmask1, kperm0, kperm1;
    h_tf2x32(0u, 42u, 0u, 0u, kmask0, kmask1);   // kmask
    h_tf2x32(0u, 42u, 0u, 1u, kperm0, kperm1);   // kperm

    // randint(kmask,...): k1,k2 = split(kmask); lower_bits keyed by k2
    uint32_t k2a, k2b;
    h_tf2x32(kmask0, kmask1, 0u, 1u, k2a, k2b);

    // permutation(kperm, 513): one sort round; subkey = split(kperm)[1]
    uint32_t sk0, sk1;
    h_tf2x32(kperm0, kperm1, 0u, 1u, sk0, sk1);

    uint32_t skeys[NCOL];
    int idx[NCOL];
    for (int c = 0; c < NCOL; c++) {
        uint32_t b1, b2;
        h_tf2x32(sk0, sk1, 0u, (uint32_t)c, b1, b2);
        skeys[c] = b1 ^ b2;                    // 32-bit fold of the 64-bit draw
        idx[c] = c;
    }
    std::stable_sort(idx, idx + NCOL,
                     [&](int a, int b) { return skeys[a] < skeys[b]; });
    PermParams P;
    P.posMid = 0; P.pad = 0;
    for (int c = 0; c < NCOL; c++) {
        int p = idx[c];
        if (p < 256)        P.posP[p] = (unsigned short)c;
        else if (p == 256)  P.posMid  = (unsigned short)c;
        else                P.posM[p - 257] = (unsigned short)c;
    }

    RotMuls RM;
    RM.m13 = 1u << 13; RM.m15 = 1u << 15; RM.m6  = 1u << 6;
    RM.m17 = 1u << 17; RM.m29 = 1u << 29; RM.m24 = 1u << 24;

    const int threads = 256;
    const int blocks = (int)(NTHREADS_TOTAL / threads);   // 16384
    crit_kernel<<<blocks, threads>>>(loc, in1, in2, out,
                                     k2a, k2b, 1u, RM, P);
}

// round 5
// speedup vs baseline: 1.4915x; 1.2189x over previous
#include <cuda_runtime.h>
#include <cstdint>
#include <algorithm>

// Problem constants
#define TPP  16
#define NCOL 513                      // 2*H*K + 1
#define EMBN 1000000
#define NTHREADS_TOTAL (1u << 21)     // NWORK/4: each thread handles 4 elements

struct PermParams {
    unsigned short posP[256];   // output column of +result[r]
    unsigned short posM[256];   // output column of -result[r]
    unsigned short posMid;      // output column of ori
    unsigned short pad;
};

// Rotation multipliers (1<<R) passed at runtime so ptxas emits IMAD.WIDE
// (fma pipe) instead of strength-reducing to SHF (alu pipe).
struct RotMuls { uint32_t m13, m26, m17, m16; };

// ---------------------------------------------------------------------------
// Threefry-2x32 (host side, for key/permutation derivation)
// ---------------------------------------------------------------------------
static inline uint32_t h_rotl32(uint32_t v, int r) {
    return (v << r) | (v >> (32 - r));
}
#define HTF_R(x0, x1, R) { x0 += x1; x1 = h_rotl32(x1, R) ^ x0; }
static void h_tf2x32(uint32_t k0, uint32_t k1, uint32_t x0, uint32_t x1,
                     uint32_t& o0, uint32_t& o1) {
    const uint32_t ks0 = k0, ks1 = k1, ks2 = k0 ^ k1 ^ 0x1BD11BDAu;
    x0 += ks0; x1 += ks1;
    HTF_R(x0, x1, 13) HTF_R(x0, x1, 15) HTF_R(x0, x1, 26) HTF_R(x0, x1, 6)
    x0 += ks1; x1 += ks2 + 1u;
    HTF_R(x0, x1, 17) HTF_R(x0, x1, 29) HTF_R(x0, x1, 16) HTF_R(x0, x1, 24)
    x0 += ks2; x1 += ks0 + 2u;
    HTF_R(x0, x1, 13) HTF_R(x0, x1, 15) HTF_R(x0, x1, 26) HTF_R(x0, x1, 6)
    x0 += ks0; x1 += ks1 + 3u;
    HTF_R(x0, x1, 17) HTF_R(x0, x1, 29) HTF_R(x0, x1, 16) HTF_R(x0, x1, 24)
    x0 += ks1; x1 += ks2 + 4u;
    HTF_R(x0, x1, 13) HTF_R(x0, x1, 15) HTF_R(x0, x1, 26) HTF_R(x0, x1, 6)
    x0 += ks2; x1 += ks0 + 5u;
    o0 = x0; o1 = x1;
}

// ---------------------------------------------------------------------------
// Main kernel: one thread per 4 adjacent elements (j = 4*tid + c, c=0..3).
// These share (level i, row t, rep k) and differ only in tp -> shared decode,
// shared gather, shared output columns, float4 stores.
// Four interleaved Threefry chains, pipe-balanced:
//   - x0-adds and key injections as IMAD via runtime `one`   (fma pipe)
//   - half the rotates via IMAD.WIDE + fused LOP3            (fma+alu)
//   - half via SHF + LOP                                     (alu)
// ---------------------------------------------------------------------------
__global__ void __launch_bounds__(256)
crit_kernel(const void* __restrict__ loc,
            const void* __restrict__ in1,
            const void* __restrict__ in2,
            float* __restrict__ out,
            uint32_t k2a, uint32_t k2b, uint32_t one,
            RotMuls RM, PermParams P) {
    const uint32_t tid = blockIdx.x * 256u + threadIdx.x;
    const uint32_t j0 = tid * 4u;

    const uint32_t tp0 = j0 & 15u;          // multiple of 4
    const uint32_t k   = (j0 >> 4) & 15u;
    const uint32_t t   = (j0 >> 8) & 2047u;
    const uint32_t i   = j0 >> 19;

    // ---- input-layout probe (uniform broadcast loads, L1-hit) ----
    const uint4 A0 = ((const uint4*)in1)[0];
    const uint4 A1 = ((const uint4*)in1)[1];
    const uint4 B0 = ((const uint4*)in2)[0];
    const uint4 B1 = ((const uint4*)in2)[1];
    const uint4 L0 = ((const uint4*)loc)[0];
    const uint4 L1 = ((const uint4*)loc)[1];
    const bool aPos = (A0.x < (1u << 20));  // pos_idx < 2^20; uniform(0,1) bits larger
    const void*  posv = aPos ? in1 : in2;
    const float* nrmp = aPos ? (const float*)in2 : (const float*)in1;
    const uint4 Pw0 = aPos ? A0 : B0;
    const uint4 Pw1 = aPos ? A1 : B1;
    const bool pos64 = ((Pw0.y | Pw0.w | Pw1.y | Pw1.w) == 0u);
    const bool loc64 = (L0.y == 0u || L0.y == 0xFFFFFFFFu) &&
                       (L0.w == 0u || L0.w == 0xFFFFFFFFu) &&
                       (L1.y == 0u || L1.y == 0xFFFFFFFFu) &&
                       (L1.w == 0u || L1.w == 0xFFFFFFFFu);

    long long pidx = pos64 ? ((const long long*)posv)[t]
                           : (long long)((const int*)posv)[t];
    if (pidx < 0) pidx = 0;
    if (pidx >= EMBN) pidx = EMBN - 1;

    int ori[4];
    if (loc64) {
        const longlong2 La = ((const longlong2*)loc)[(pidx * TPP + tp0) >> 1];
        const longlong2 Lb = ((const longlong2*)loc)[((pidx * TPP + tp0) >> 1) + 1];
        ori[0] = (int)La.x; ori[1] = (int)La.y;
        ori[2] = (int)Lb.x; ori[3] = (int)Lb.y;
    } else {
        const int4 L = ((const int4*)loc)[(pidx * TPP + tp0) >> 2];
        ori[0] = L.x; ori[1] = L.y; ori[2] = L.z; ori[3] = L.w;
    }
    const float nrm = nrmp[t];

    // ---- quad Threefry-2x32, 20 rounds ----
    const uint32_t ks0 = k2a, ks1 = k2b, ks2 = k2a ^ k2b ^ 0x1BD11BDAu;
    const uint32_t c1B = ks2 + 1u, c2B = ks0 + 2u, c3B = ks1 + 3u,
                   c4B = ks2 + 4u, c5B = ks0 + 5u;

    uint32_t x0[4], x1[4];
    #pragma unroll
    for (int c = 0; c < 4; c++) { x0[c] = ks0; x1[c] = (j0 + (uint32_t)c) + ks1; }

#define QADD(a, b) ((a) * one + (b))                     /* IMAD, fma pipe */
#define RW_ALL(M) _Pragma("unroll") for (int c = 0; c < 4; c++) {              \
    x0[c] = QADD(x0[c], x1[c]);                                                \
    uint64_t w_ = (uint64_t)x1[c] * (uint64_t)(M);       /* IMAD.WIDE */       \
    x1[c] = ((uint32_t)(w_ >> 32) | (uint32_t)w_) ^ x0[c]; /* fused LOP3 */    \
}
#define RS_ALL(R) _Pragma("unroll") for (int c = 0; c < 4; c++) {              \
    x0[c] = QADD(x0[c], x1[c]);                                                \
    x1[c] = __funnelshift_l(x1[c], x1[c], (R)) ^ x0[c];  /* SHF + LOP */       \
}
#define INJ_ALL(cA, cB) _Pragma("unroll") for (int c = 0; c < 4; c++) {        \
    x0[c] = QADD(x0[c], (cA)); x1[c] = QADD(x1[c], (cB));  /* IMAD x2 */       \
}
// Group A rotations: 13,15,26,6  -> wide,shift,wide,shift
#define GRP_A  RW_ALL(RM.m13) RS_ALL(15) RW_ALL(RM.m26) RS_ALL(6)
// Group B rotations: 17,29,16,24 -> wide,shift,wide,shift
#define GRP_B  RW_ALL(RM.m17) RS_ALL(29) RW_ALL(RM.m16) RS_ALL(24)

    GRP_A
    INJ_ALL(ks1, c1B)
    GRP_B
    INJ_ALL(ks2, c2B)
    GRP_A
    INJ_ALL(ks0, c3B)
    GRP_B
    INJ_ALL(ks1, c4B)
    GRP_A
    // final: only o1 needed
    uint32_t b2[4];
    #pragma unroll
    for (int c = 0; c < 4; c++) b2[c] = QADD(x1[c], c5B);

    // ---- candidates + distance (sign via bit XOR, e via FLO+I2F+FFMA) ----
    const uint32_t lvlmask = (1u << i) - 1u;
    const int flip = (int)(1u << i);
    const float n16  = nrm * 0.0625f;
    const float mnrm = -nrm;

    float vp[4], vm[4];
    #pragma unroll
    for (int c = 0; c < 4; c++) {
        const int o = ori[c];
        const int cand = o ^ flip ^ (int)(b2[c] & lvlmask);
        const uint32_t ax = (uint32_t)(abs(cand) ^ abs(o));
        const int q = __clz(ax + 1u);                       // e = 32 - q
        const float base = fmaf((float)q, n16, mnrm);       // (q/16 - 1)*nrm... 
        // base = q*nrm/16 - nrm = -(1 - (32-e... ) check: q=32-e -> base = (32-e)/16*nrm - nrm
        //      = (2 - e/16 - 1)*nrm = (1 - e/16)*nrm  ✓
        const uint32_t sb = 0x80000000u;
        const uint32_t sp = ((uint32_t)(cand ^ o)) & sb;    // sign(+cand)*sign(ori)
        const uint32_t sm = ((uint32_t)((-cand) ^ o)) & sb; // sign(-cand)*sign(ori)
        vp[c] = __uint_as_float(__float_as_uint(base) ^ sp);
        vm[c] = __uint_as_float(__float_as_uint(base) ^ sm);
    }

    // ---- scatter via precomputed permutation (float4 per column) ----
    const int r = (int)(i * 16u + k);
    float* row = out + (size_t)t * (NCOL * TPP) + tp0;
    *(float4*)(row + (int)P.posP[r] * TPP) = make_float4(vp[0], vp[1], vp[2], vp[3]);
    *(float4*)(row + (int)P.posM[r] * TPP) = make_float4(vm[0], vm[1], vm[2], vm[3]);
    if (r == 0) {
        const float mid = 0.9375f * nrm;       // (1 - 1/16) * norm
        *(float4*)(row + (int)P.posMid * TPP) = make_float4(mid, mid, mid, mid);
    }
}

// ---------------------------------------------------------------------------
// Host: derive Threefry keys + 513-column permutation (deterministic).
// ---------------------------------------------------------------------------
extern "C" void kernel_launch(void* const* d_in, const int* in_sizes, int n_in,
                              void* d_out, int out_size) {
    const void* loc = d_in[0];          // locations (EMB, 16)
    const void* in1 = d_in[1];
    const void* in2 = d_in[2];
    float* out = (float*)d_out;

    // key = jax.random.key(42) -> (0, 42); partitionable split(key)[i] = TF(key,(0,i))
    uint32_t kmask0, kmask1, kperm0, kperm1;
    h_tf2x32(0u, 42u, 0u, 0u, kmask0, kmask1);   // kmask
    h_tf2x32(0u, 42u, 0u, 1u, kperm0, kperm1);   // kperm

    // randint(kmask,...): k1,k2 = split(kmask); lower_bits keyed by k2
    uint32_t k2a, k2b;
    h_tf2x32(kmask0, kmask1, 0u, 1u, k2a, k2b);

    // permutation(kperm, 513): one sort round; subkey = split(kperm)[1]
    uint32_t sk0, sk1;
    h_tf2x32(kperm0, kperm1, 0u, 1u, sk0, sk1);

    uint32_t skeys[NCOL];
    int idx[NCOL];
    for (int c = 0; c < NCOL; c++) {
        uint32_t b1, b2;
        h_tf2x32(sk0, sk1, 0u, (uint32_t)c, b1, b2);
        skeys[c] = b1 ^ b2;                    // 32-bit fold of the 64-bit draw
        idx[c] = c;
    }
    std::stable_sort(idx, idx + NCOL,
                     [&](int a, int b) { return skeys[a] < skeys[b]; });
    PermParams P;
    P.posMid = 0; P.pad = 0;
    for (int c = 0; c < NCOL; c++) {
        int p = idx[c];
        if (p < 256)        P.posP[p] = (unsigned short)c;
        else if (p == 256)  P.posMid  = (unsigned short)c;
        else                P.posM[p - 257] = (unsigned short)c;
    }

    RotMuls RM;
    RM.m13 = 1u << 13; RM.m26 = 1u << 26;
    RM.m17 = 1u << 17; RM.m16 = 1u << 16;

    const int threads = 256;
    const int blocks = (int)(NTHREADS_TOTAL / threads);   // 8192
    crit_kernel<<<blocks, threads>>>(loc, in1, in2, out,
                                     k2a, k2b, 1u, RM, P);
}

// round 7
// speedup vs baseline: 1.5746x; 1.0558x over previous
#include <cuda_runtime.h>
#include <cstdint>
#include <algorithm>

// Problem constants
#define TPP  16
#define NCOL 513                      // 2*H*K + 1
#define EMBN 1000000
#define NTHREADS_TOTAL (1u << 21)     // NWORK/4: each thread handles 4 elements

struct PermParams {
    unsigned short posP[256];   // output column of +result[r]
    unsigned short posM[256];   // output column of -result[r]
    unsigned short posMid;      // output column of ori
    unsigned short pad;
};

// Rotation multipliers (1<<R) passed at runtime -> IMAD.WIDE on fma pipe.
struct RotMuls { uint32_t m13, m26, m17, m16; };

// ---------------------------------------------------------------------------
// Threefry-2x32 (host side, for key/permutation derivation)
// ---------------------------------------------------------------------------
static inline uint32_t h_rotl32(uint32_t v, int r) {
    return (v << r) | (v >> (32 - r));
}
#define HTF_R(x0, x1, R) { x0 += x1; x1 = h_rotl32(x1, R) ^ x0; }
static void h_tf2x32(uint32_t k0, uint32_t k1, uint32_t x0, uint32_t x1,
                     uint32_t& o0, uint32_t& o1) {
    const uint32_t ks0 = k0, ks1 = k1, ks2 = k0 ^ k1 ^ 0x1BD11BDAu;
    x0 += ks0; x1 += ks1;
    HTF_R(x0, x1, 13) HTF_R(x0, x1, 15) HTF_R(x0, x1, 26) HTF_R(x0, x1, 6)
    x0 += ks1; x1 += ks2 + 1u;
    HTF_R(x0, x1, 17) HTF_R(x0, x1, 29) HTF_R(x0, x1, 16) HTF_R(x0, x1, 24)
    x0 += ks2; x1 += ks0 + 2u;
    HTF_R(x0, x1, 13) HTF_R(x0, x1, 15) HTF_R(x0, x1, 26) HTF_R(x0, x1, 6)
    x0 += ks0; x1 += ks1 + 3u;
    HTF_R(x0, x1, 17) HTF_R(x0, x1, 29) HTF_R(x0, x1, 16) HTF_R(x0, x1, 24)
    x0 += ks1; x1 += ks2 + 4u;
    HTF_R(x0, x1, 13) HTF_R(x0, x1, 15) HTF_R(x0, x1, 26) HTF_R(x0, x1, 6)
    x0 += ks2; x1 += ks0 + 5u;
    o0 = x0; o1 = x1;
}

// ---------------------------------------------------------------------------
// Main kernel: one thread per 4 adjacent elements (j = 4*tid + c, c=0..3).
// These share (level i, row t, rep k), differ only in tp -> shared decode,
// shared gather, shared output columns, float4 stores.
// Four interleaved Threefry chains. Key injections folded into the following
// round's x0-add via IADD3. Level 0 (mask==0) skips Threefry entirely
// (block-uniform branch).
// Sign property: cand = ori ^ D with D < 2^16 keeps bit31 -> sign(cand) ==
// sign(ori) -> vp = +base always; vm = base ^ signbit(cand | -cand).
// ---------------------------------------------------------------------------
__global__ void __launch_bounds__(256)
crit_kernel(const void* __restrict__ loc,
            const void* __restrict__ in1,
            const void* __restrict__ in2,
            float* __restrict__ out,
            uint32_t k2a, uint32_t k2b, uint32_t one,
            RotMuls RM, PermParams P) {
    const uint32_t tid = blockIdx.x * 256u + threadIdx.x;
    const uint32_t j0 = tid * 4u;

    const uint32_t tp0 = j0 & 15u;          // multiple of 4
    const uint32_t k   = (j0 >> 4) & 15u;
    const uint32_t t   = (j0 >> 8) & 2047u;
    const uint32_t i   = j0 >> 19;

    // ---- input-layout probe (uniform broadcast loads, L1-hit) ----
    const uint4 A0 = ((const uint4*)in1)[0];
    const uint4 A1 = ((const uint4*)in1)[1];
    const uint4 B0 = ((const uint4*)in2)[0];
    const uint4 B1 = ((const uint4*)in2)[1];
    const uint4 L0 = ((const uint4*)loc)[0];
    const uint4 L1 = ((const uint4*)loc)[1];
    const bool aPos = (A0.x < (1u << 20));  // pos_idx < 2^20; uniform(0,1) bits larger
    const void*  posv = aPos ? in1 : in2;
    const float* nrmp = aPos ? (const float*)in2 : (const float*)in1;
    const uint4 Pw0 = aPos ? A0 : B0;
    const uint4 Pw1 = aPos ? A1 : B1;
    const bool pos64 = ((Pw0.y | Pw0.w | Pw1.y | Pw1.w) == 0u);
    const bool loc64 = (L0.y == 0u || L0.y == 0xFFFFFFFFu) &&
                       (L0.w == 0u || L0.w == 0xFFFFFFFFu) &&
                       (L1.y == 0u || L1.y == 0xFFFFFFFFu) &&
                       (L1.w == 0u || L1.w == 0xFFFFFFFFu);

    long long pidx = pos64 ? ((const long long*)posv)[t]
                           : (long long)((const int*)posv)[t];
    if (pidx < 0) pidx = 0;
    if (pidx >= EMBN) pidx = EMBN - 1;

    int ori[4];
    if (loc64) {
        const longlong2 La = ((const longlong2*)loc)[(pidx * TPP + tp0) >> 1];
        const longlong2 Lb = ((const longlong2*)loc)[((pidx * TPP + tp0) >> 1) + 1];
        ori[0] = (int)La.x; ori[1] = (int)La.y;
        ori[2] = (int)Lb.x; ori[3] = (int)Lb.y;
    } else {
        const int4 L = ((const int4*)loc)[(pidx * TPP + tp0) >> 2];
        ori[0] = L.x; ori[1] = L.y; ori[2] = L.z; ori[3] = L.w;
    }
    const float nrm = nrmp[t];

    // ---- quad Threefry-2x32, 20 rounds, injections folded ----
    const uint32_t ks0 = k2a, ks1 = k2b, ks2 = k2a ^ k2b ^ 0x1BD11BDAu;
    const uint32_t c1B = ks2 + 1u, c2B = ks0 + 2u, c3B = ks1 + 3u,
                   c4B = ks2 + 4u, c5B = ks0 + 5u;

    uint32_t b2[4] = {0u, 0u, 0u, 0u};

#define QADD(a, b) ((a) * one + (b))                     /* IMAD, fma pipe */
#define RW_ALL(M) _Pragma("unroll") for (int c = 0; c < 4; c++) {              \
    x0[c] = QADD(x0[c], x1[c]);                                                \
    uint64_t w_ = (uint64_t)x1[c] * (uint64_t)(M);       /* IMAD.WIDE */       \
    x1[c] = ((uint32_t)(w_ >> 32) | (uint32_t)w_) ^ x0[c]; /* fused LOP3 */    \
}
#define RS_ALL(R) _Pragma("unroll") for (int c = 0; c < 4; c++) {              \
    x0[c] = QADD(x0[c], x1[c]);                                                \
    x1[c] = __funnelshift_l(x1[c], x1[c], (R)) ^ x0[c];  /* SHF + LOP */       \
}
// Injection (cA into x0, cB into x1) folded into the round's x0-add: IADD3.
#define RW_INJ_ALL(M, cA, cB) _Pragma("unroll") for (int c = 0; c < 4; c++) {  \
    x1[c] = QADD(x1[c], (cB));                                                 \
    x0[c] = (x0[c] + (cA)) + x1[c];                      /* IADD3 */           \
    uint64_t w_ = (uint64_t)x1[c] * (uint64_t)(M);                             \
    x1[c] = ((uint32_t)(w_ >> 32) | (uint32_t)w_) ^ x0[c];                     \
}
#define GRP_A0            RW_ALL(RM.m13)            RS_ALL(15) RW_ALL(RM.m26) RS_ALL(6)
#define GRP_A_INJ(cA, cB) RW_INJ_ALL(RM.m13, cA, cB) RS_ALL(15) RW_ALL(RM.m26) RS_ALL(6)
#define GRP_B_INJ(cA, cB) RW_INJ_ALL(RM.m17, cA, cB) RS_ALL(29) RW_ALL(RM.m16) RS_ALL(24)

    if (i != 0) {       // level 0 has mask 0: Threefry output unused
        uint32_t x0[4], x1[4];
        #pragma unroll
        for (int c = 0; c < 4; c++) { x0[c] = ks0; x1[c] = (j0 + (uint32_t)c) + ks1; }
        GRP_A0
        GRP_B_INJ(ks1, c1B)
        GRP_A_INJ(ks2, c2B)
        GRP_B_INJ(ks0, c3B)
        GRP_A_INJ(ks1, c4B)
        #pragma unroll
        for (int c = 0; c < 4; c++) b2[c] = QADD(x1[c], c5B);
    }

    // ---- candidates + distance ----
    const uint32_t lvlmask = (1u << i) - 1u;
    const uint32_t flip = 1u << i;
    const float n16  = nrm * 0.0625f;
    const float mnrm = -nrm;

    float vp[4], vm[4];
    #pragma unroll
    for (int c = 0; c < 4; c++) {
        const int o = ori[c];
        const uint32_t D = (b2[c] & lvlmask) ^ flip;        // one LOP3; i==0 -> D=1
        const int cand = o ^ (int)D;                        // sign(cand)==sign(o)
        const uint32_t ax = (uint32_t)(abs(cand) ^ abs(o));
        const int q = __clz(ax + 1u);                       // e = 32 - q
        const float base = fmaf((float)q, n16, mnrm);       // (1 - e/16) * nrm
        // vm = -base unless cand == 0 (then sign(-cand)=+1 -> +base)
        const uint32_t s = (uint32_t)(cand | -cand) & 0x80000000u;
        vp[c] = base;
        vm[c] = __uint_as_float(__float_as_uint(base) ^ s);
    }

    // ---- scatter via precomputed permutation (float4 per column) ----
    const int r = (int)(i * 16u + k);
    float* row = out + (size_t)t * (NCOL * TPP) + tp0;
    *(float4*)(row + (int)P.posP[r] * TPP) = make_float4(vp[0], vp[1], vp[2], vp[3]);
    *(float4*)(row + (int)P.posM[r] * TPP) = make_float4(vm[0], vm[1], vm[2], vm[3]);
    if (r == 0) {
        const float mid = 0.9375f * nrm;       // (1 - 1/16) * norm
        *(float4*)(row + (int)P.posMid * TPP) = make_float4(mid, mid, mid, mid);
    }
}

// ---------------------------------------------------------------------------
// Host: derive Threefry keys + 513-column permutation (deterministic).
// ---------------------------------------------------------------------------
extern "C" void kernel_launch(void* const* d_in, const int* in_sizes, int n_in,
                              void* d_out, int out_size) {
    const void* loc = d_in[0];          // locations (EMB, 16)
    const void* in1 = d_in[1];
    const void* in2 = d_in[2];
    float* out = (float*)d_out;

    // key = jax.random.key(42) -> (0, 42); partitionable split(key)[i] = TF(key,(0,i))
    uint32_t kmask0, kmask1, kperm0, kperm1;
    h_tf2x32(0u, 42u, 0u, 0u, kmask0, kmask1);   // kmask
    h_tf2x32(0u, 42u, 0u, 1u, kperm0, kperm1);   // kperm

    // randint(kmask,...): k1,k2 = split(kmask); lower_bits keyed by k2
    uint32_t k2a, k2b;
    h_tf2x32(kmask0, kmask1, 0u, 1u, k2a, k2b);

    // permutation(kperm, 513): one sort round; subkey = split(kperm)[1]
    uint32_t sk0, sk1;
    h_tf2x32(kperm0, kperm1, 0u, 1u, sk0, sk1);

    uint32_t skeys[NCOL];
    int idx[NCOL];
    for (int c = 0; c < NCOL; c++) {
        uint32_t b1, b2;
        h_tf2x32(sk0, sk1, 0u, (uint32_t)c, b1, b2);
        skeys[c] = b1 ^ b2;                    // 32-bit fold of the 64-bit draw
        idx[c] = c;
    }
    std::stable_sort(idx, idx + NCOL,
                     [&](int a, int b) { return skeys[a] < skeys[b]; });
    PermParams P;
    P.posMid = 0; P.pad = 0;
    for (int c = 0; c < NCOL; c++) {
        int p = idx[c];
        if (p < 256)        P.posP[p] = (unsigned short)c;
        else if (p == 256)  P.posMid  = (unsigned short)c;
        else                P.posM[p - 257] = (unsigned short)c;
    }

    RotMuls RM;
    RM.m13 = 1u << 13; RM.m26 = 1u << 26;
    RM.m17 = 1u << 17; RM.m16 = 1u << 16;

    const int threads = 256;
    const int blocks = (int)(NTHREADS_TOTAL / threads);   // 8192
    crit_kernel<<<blocks, threads>>>(loc, in1, in2, out,
                                     k2a, k2b, 1u, RM, P);
}

// round 8
// speedup vs baseline: 1.5875x; 1.0082x over previous
#include <cuda_runtime.h>
#include <cstdint>
#include <algorithm>

// Problem constants
#define TPP  16
#define NCOL 513                      // 2*H*K + 1
#define EMBN 1000000
#define NTHREADS_TOTAL (1u << 20)     // NWORK/8: each thread handles 8 elements

struct PermParams {
    unsigned short posP[256];   // output column of +result[r]
    unsigned short posM[256];   // output column of -result[r]
    unsigned short posMid;      // output column of ori
    unsigned short pad;
};

// Rotation multipliers (1<<R) passed at runtime -> IMAD.WIDE on fma pipe.
struct RotMuls { uint32_t m13, m15, m26, m17, m29, m24; };

// ---------------------------------------------------------------------------
// Threefry-2x32 (host side, for key/permutation derivation)
// ---------------------------------------------------------------------------
static inline uint32_t h_rotl32(uint32_t v, int r) {
    return (v << r) | (v >> (32 - r));
}
#define HTF_R(x0, x1, R) { x0 += x1; x1 = h_rotl32(x1, R) ^ x0; }
static void h_tf2x32(uint32_t k0, uint32_t k1, uint32_t x0, uint32_t x1,
                     uint32_t& o0, uint32_t& o1) {
    const uint32_t ks0 = k0, ks1 = k1, ks2 = k0 ^ k1 ^ 0x1BD11BDAu;
    x0 += ks0; x1 += ks1;
    HTF_R(x0, x1, 13) HTF_R(x0, x1, 15) HTF_R(x0, x1, 26) HTF_R(x0, x1, 6)
    x0 += ks1; x1 += ks2 + 1u;
    HTF_R(x0, x1, 17) HTF_R(x0, x1, 29) HTF_R(x0, x1, 16) HTF_R(x0, x1, 24)
    x0 += ks2; x1 += ks0 + 2u;
    HTF_R(x0, x1, 13) HTF_R(x0, x1, 15) HTF_R(x0, x1, 26) HTF_R(x0, x1, 6)
    x0 += ks0; x1 += ks1 + 3u;
    HTF_R(x0, x1, 17) HTF_R(x0, x1, 29) HTF_R(x0, x1, 16) HTF_R(x0, x1, 24)
    x0 += ks1; x1 += ks2 + 4u;
    HTF_R(x0, x1, 13) HTF_R(x0, x1, 15) HTF_R(x0, x1, 26) HTF_R(x0, x1, 6)
    x0 += ks2; x1 += ks0 + 5u;
    o0 = x0; o1 = x1;
}

// ---------------------------------------------------------------------------
// Main kernel: one thread per 8 adjacent elements (j = 8*tid + c, c=0..7).
// These share (level i, row t, rep k); tp0 in {0, 8}. Shared decode, shared
// gather (warp-wide it's ONE pidx -> 128/256B broadcast), shared output
// columns, float4 stores. Eight interleaved Threefry chains for ILP.
// 15 of 20 rotates via IMAD.WIDE (fma pipe), 5 via SHF (alu pipe).
// Key injections folded into the next round's x0-add (IADD3).
// Level 0 (mask==0) skips Threefry entirely (block-uniform branch).
// Sign property: cand = ori ^ D with D < 2^16 keeps bit31 -> sign(cand) ==
// sign(ori) -> vp = +base; vm = base ^ signbit(cand | -cand).
// ---------------------------------------------------------------------------
__global__ void __launch_bounds__(256)
crit_kernel(const void* __restrict__ loc,
            const void* __restrict__ in1,
            const void* __restrict__ in2,
            float* __restrict__ out,
            uint32_t k2a, uint32_t k2b, uint32_t one,
            RotMuls RM, PermParams P) {
    const uint32_t tid = blockIdx.x * 256u + threadIdx.x;
    const uint32_t j0 = tid * 8u;

    const uint32_t tp0 = j0 & 15u;          // 0 or 8
    const uint32_t k   = (j0 >> 4) & 15u;
    const uint32_t t   = (j0 >> 8) & 2047u;
    const uint32_t i   = j0 >> 19;

    // ---- input-layout probe (uniform broadcast loads, L1-hit) ----
    const uint4 A0 = ((const uint4*)in1)[0];
    const uint4 A1 = ((const uint4*)in1)[1];
    const uint4 B0 = ((const uint4*)in2)[0];
    const uint4 B1 = ((const uint4*)in2)[1];
    const uint4 L0 = ((const uint4*)loc)[0];
    const uint4 L1 = ((const uint4*)loc)[1];
    const bool aPos = (A0.x < (1u << 20));  // pos_idx < 2^20; uniform(0,1) bits larger
    const void*  posv = aPos ? in1 : in2;
    const float* nrmp = aPos ? (const float*)in2 : (const float*)in1;
    const uint4 Pw0 = aPos ? A0 : B0;
    const uint4 Pw1 = aPos ? A1 : B1;
    const bool pos64 = ((Pw0.y | Pw0.w | Pw1.y | Pw1.w) == 0u);
    const bool loc64 = (L0.y == 0u || L0.y == 0xFFFFFFFFu) &&
                       (L0.w == 0u || L0.w == 0xFFFFFFFFu) &&
                       (L1.y == 0u || L1.y == 0xFFFFFFFFu) &&
                       (L1.w == 0u || L1.w == 0xFFFFFFFFu);

    long long pidx = pos64 ? ((const long long*)posv)[t]
                           : (long long)((const int*)posv)[t];
    if (pidx < 0) pidx = 0;
    if (pidx >= EMBN) pidx = EMBN - 1;

    int ori[8];
    if (loc64) {
        const size_t base = (size_t)(pidx * TPP + tp0) >> 1;   // longlong2 index
        #pragma unroll
        for (int h = 0; h < 4; h++) {
            const longlong2 L = ((const longlong2*)loc)[base + h];
            ori[2*h]   = (int)L.x;
            ori[2*h+1] = (int)L.y;
        }
    } else {
        const size_t base = (size_t)(pidx * TPP + tp0) >> 2;   // int4 index
        const int4 La = ((const int4*)loc)[base];
        const int4 Lb = ((const int4*)loc)[base + 1];
        ori[0] = La.x; ori[1] = La.y; ori[2] = La.z; ori[3] = La.w;
        ori[4] = Lb.x; ori[5] = Lb.y; ori[6] = Lb.z; ori[7] = Lb.w;
    }
    const float nrm = nrmp[t];

    // ---- oct Threefry-2x32, 20 rounds, injections folded ----
    const uint32_t ks0 = k2a, ks1 = k2b, ks2 = k2a ^ k2b ^ 0x1BD11BDAu;
    const uint32_t c1B = ks2 + 1u, c2B = ks0 + 2u, c3B = ks1 + 3u,
                   c4B = ks2 + 4u, c5B = ks0 + 5u;

    uint32_t b2[8];
    #pragma unroll
    for (int c = 0; c < 8; c++) b2[c] = 0u;

#define QADD(a, b) ((a) * one + (b))                     /* IMAD, fma pipe */
#define RW_ALL(M) _Pragma("unroll") for (int c = 0; c < 8; c++) {              \
    x0[c] = QADD(x0[c], x1[c]);                                                \
    uint64_t w_ = (uint64_t)x1[c] * (uint64_t)(M);       /* IMAD.WIDE */       \
    x1[c] = ((uint32_t)(w_ >> 32) | (uint32_t)w_) ^ x0[c]; /* fused LOP3 */    \
}
#define RS_ALL(R) _Pragma("unroll") for (int c = 0; c < 8; c++) {              \
    x0[c] = QADD(x0[c], x1[c]);                                                \
    x1[c] = __funnelshift_l(x1[c], x1[c], (R)) ^ x0[c];  /* SHF + LOP */       \
}
// Injection (cA into x0, cB into x1) folded into the round's x0-add: IADD3.
#define RW_INJ_ALL(M, cA, cB) _Pragma("unroll") for (int c = 0; c < 8; c++) {  \
    x1[c] = QADD(x1[c], (cB));                                                 \
    x0[c] = (x0[c] + (cA)) + x1[c];                      /* IADD3 */           \
    uint64_t w_ = (uint64_t)x1[c] * (uint64_t)(M);                             \
    x1[c] = ((uint32_t)(w_ >> 32) | (uint32_t)w_) ^ x0[c];                     \
}
// Group A rotations 13,15,26,6 -> W,W,S,W ; Group B rotations 17,29,16,24 -> W,S,W,W
#define GRP_A0            RW_ALL(RM.m13)             RW_ALL(RM.m15) RS_ALL(26) RW_ALL(RM.m26 /*unused*/)
// NOTE: cannot reuse names loosely -- define explicitly below instead.
#undef GRP_A0

#define GRP_A_FIRST       RW_ALL(RM.m13)              RW_ALL(RM.m15) RS_ALL(26) RW_ALL((1u<<6)*one + 0u)
#undef GRP_A_FIRST
// (multipliers must come from RM so ptxas can't strength-reduce; define m6 via m26>>? no --
//  pass all six multipliers in RM.)

#define GA0            RW_ALL(RM.m13)              RW_ALL(RM.m15) RS_ALL(26) RW_ALL(RM.m26)
#define GA_INJ(cA, cB) RW_INJ_ALL(RM.m13, cA, cB)  RW_ALL(RM.m15) RS_ALL(26) RW_ALL(RM.m26)
#define GB_INJ(cA, cB) RW_INJ_ALL(RM.m17, cA, cB)  RS_ALL(29)     RW_ALL(RM.m29) RW_ALL(RM.m24)

    // RM fields: m13=1<<13, m15=1<<15, m26=1<<6 (A-group last rotate is 6!),
    //            m17=1<<17, m29=1<<16 (B-group third rotate is 16!), m24=1<<24.
    // (Names kept from struct; host fills with the correct shift amounts.)

    if (i != 0) {       // level 0 has mask 0: Threefry output unused
        uint32_t x0[8], x1[8];
        #pragma unroll
        for (int c = 0; c < 8; c++) { x0[c] = ks0; x1[c] = (j0 + (uint32_t)c) + ks1; }
        GA0                      // rounds 1-4:   rot 13,15,26,6
        GB_INJ(ks1, c1B)         // rounds 5-8:   rot 17,29,16,24
        GA_INJ(ks2, c2B)         // rounds 9-12
        GB_INJ(ks0, c3B)         // rounds 13-16
        GA_INJ(ks1, c4B)         // rounds 17-20
        #pragma unroll
        for (int c = 0; c < 8; c++) b2[c] = QADD(x1[c], c5B);
    }

    // ---- candidates + distance ----
    const uint32_t lvlmask = (1u << i) - 1u;
    const uint32_t flip = 1u << i;
    const float n16  = nrm * 0.0625f;
    const float mnrm = -nrm;

    float vp[8], vm[8];
    #pragma unroll
    for (int c = 0; c < 8; c++) {
        const int o = ori[c];
        const uint32_t D = (b2[c] & lvlmask) ^ flip;        // one LOP3; i==0 -> D=1
        const int cand = o ^ (int)D;                        // sign(cand)==sign(o)
        const uint32_t ax = (uint32_t)(abs(cand) ^ abs(o));
        const int q = __clz(ax + 1u);                       // e = 32 - q
        const float base = fmaf((float)q, n16, mnrm);       // (1 - e/16) * nrm
        // vm = -base unless cand == 0 (then sign(-cand)=+1 -> +base)
        const uint32_t s = (uint32_t)(cand | -cand) & 0x80000000u;
        vp[c] = base;
        vm[c] = __uint_as_float(__float_as_uint(base) ^ s);
    }

    // ---- scatter via precomputed permutation (2x float4 per column) ----
    const int r = (int)(i * 16u + k);
    float* row = out + (size_t)t * (NCOL * TPP) + tp0;
    float* rp = row + (int)P.posP[r] * TPP;
    float* rm = row + (int)P.posM[r] * TPP;
    *(float4*)(rp)     = make_float4(vp[0], vp[1], vp[2], vp[3]);
    *(float4*)(rp + 4) = make_float4(vp[4], vp[5], vp[6], vp[7]);
    *(float4*)(rm)     = make_float4(vm[0], vm[1], vm[2], vm[3]);
    *(float4*)(rm + 4) = make_float4(vm[4], vm[5], vm[6], vm[7]);
    if (r == 0) {
        const float mid = 0.9375f * nrm;       // (1 - 1/16) * norm
        float* rq = row + (int)P.posMid * TPP;
        *(float4*)(rq)     = make_float4(mid, mid, mid, mid);
        *(float4*)(rq + 4) = make_float4(mid, mid, mid, mid);
    }
}

// ---------------------------------------------------------------------------
// Host: derive Threefry keys + 513-column permutation (deterministic).
// ---------------------------------------------------------------------------
extern "C" void kernel_launch(void* const* d_in, const int* in_sizes, int n_in,
                              void* d_out, int out_size) {
    const void* loc = d_in[0];          // locations (EMB, 16)
    const void* in1 = d_in[1];
    const void* in2 = d_in[2];
    float* out = (float*)d_out;

    // key = jax.random.key(42) -> (0, 42); partitionable split(key)[i] = TF(key,(0,i))
    uint32_t kmask0, kmask1, kperm0, kperm1;
    h_tf2x32(0u, 42u, 0u, 0u, kmask0, kmask1);   // kmask
    h_tf2x32(0u, 42u, 0u, 1u, kperm0, kperm1);   // kperm

    // randint(kmask,...): k1,k2 = split(kmask); lower_bits keyed by k2
    uint32_t k2a, k2b;
    h_tf2x32(kmask0, kmask1, 0u, 1u, k2a, k2b);

    // permutation(kperm, 513): one sort round; subkey = split(kperm)[1]
    uint32_t sk0, sk1;
    h_tf2x32(kperm0, kperm1, 0u, 1u, sk0, sk1);

    uint32_t skeys[NCOL];
    int idx[NCOL];
    for (int c = 0; c < NCOL; c++) {
        uint32_t b1, b2;
        h_tf2x32(sk0, sk1, 0u, (uint32_t)c, b1, b2);
        skeys[c] = b1 ^ b2;                    // 32-bit fold of the 64-bit draw
        idx[c] = c;
    }
    std::stable_sort(idx, idx + NCOL,
                     [&](int a, int b) { return skeys[a] < skeys[b]; });
    PermParams P;
    P.posMid = 0; P.pad = 0;
    for (int c = 0; c < NCOL; c++) {
        int p = idx[c];
        if (p < 256)        P.posP[p] = (unsigned short)c;
        else if (p == 256)  P.posMid  = (unsigned short)c;
        else                P.posM[p - 257] = (unsigned short)c;
    }

    // Rotation multipliers in GROUP ORDER (see GA/GB macros):
    //   GA rounds: rot 13 (inj/wide), 15 (wide), 26 (shift), 6 (wide)
    //   GB rounds: rot 17 (inj/wide), 29 (shift), 16 (wide), 24 (wide)
    RotMuls RM;
    RM.m13 = 1u << 13;   // GA round 1
    RM.m15 = 1u << 15;   // GA round 2
    RM.m26 = 1u << 6;    // GA round 4 (rotate-by-6; field name historical)
    RM.m17 = 1u << 17;   // GB round 1
    RM.m29 = 1u << 16;   // GB round 3 (rotate-by-16; field name historical)
    RM.m24 = 1u << 24;   // GB round 4

    const int threads = 256;
    const int blocks = (int)(NTHREADS_TOTAL / threads);   // 4096
    crit_kernel<<<blocks, threads>>>(loc, in1, in2, out,
                                     k2a, k2b, 1u, RM, P);
}